// round 9
// baseline (speedup 1.0000x reference)
#include <cuda_runtime.h>

#define Dd 256
#define Nn 1024
#define Mm 1024
#define RG 8                  // rows per K1 tile
#define CT 128                // cols per K1 tile
#define NGRP 256              // 4-row column-partial groups (1024/4)
#define K3_BLOCKS 128

typedef unsigned long long u64;
typedef unsigned int u32;

// Scratch (static __device__ — no runtime allocation)
__device__ float g_S[Nn * Mm];            // score matrix s = -L1dist (4 MB)
__device__ float g_pm[Mm * NGRP];         // col partial max, transposed [col][group]
__device__ float g_ps[Mm * NGRP];         // col partial expsum
__device__ float g_cm[Mm], g_cinv[Mm];    // column max, 1/colsum
__device__ float g_num[Nn], g_den[Nn];    // per-row final partials
__device__ u32 g_done = 0;                // k3 last-block counter (self-resetting)

#define FMA2(o, a, b, c) asm("fma.rn.f32x2 %0, %1, %2, %3;" : "=l"(o) : "l"(a), "l"(b), "l"(c))
#define ADD2(o, a, b)    asm("add.rn.f32x2 %0, %1, %2;"     : "=l"(o) : "l"(a), "l"(b))

__device__ __forceinline__ float lo32(u64 v) { return __uint_as_float((u32)v); }
__device__ __forceinline__ float hi32(u64 v) { return __uint_as_float((u32)(v >> 32)); }

__device__ __forceinline__ float warpMax(float v) {
    #pragma unroll
    for (int o = 16; o; o >>= 1) v = fmaxf(v, __shfl_xor_sync(0xffffffffu, v, o));
    return v;
}
__device__ __forceinline__ float warpSum(float v) {
    #pragma unroll
    for (int o = 16; o; o >>= 1) v += __shfl_xor_sync(0xffffffffu, v, o);
    return v;
}

// ===================== K1: scores + per-4-row-group column partials =====================
// 1024 blocks (128 row-groups x 8 col-tiles), 128 threads.
// Thread t: col pair cp = t&63 (cols j0+2cp, j0+2cp+1), rows rp4..rp4+3 (rp4 = (t>>6)*4).
// Mainloop: 8-d unrolled body, pointer+immediate addressing, depth-8 y prefetch
// interleaved through the body, x consumed directly from smem (broadcast LDS.128).
__global__ __launch_bounds__(128, 8) void k1_scores(
    const float* __restrict__ zx, const float* __restrict__ zy)
{
    __shared__ __align__(16) float2 xs[Dd][RG];   // duplicated (x,x) pairs, 16KB
    const int t = threadIdx.x;
    const int rg = blockIdx.x >> 3;
    const int ct = blockIdx.x & 7;
    const int i0 = rg * RG, j0 = ct * CT;

    for (int idx = t; idx < Dd * RG; idx += 128) {
        int d = idx >> 3, r = idx & 7;
        float v = zx[d * Nn + i0 + r];
        xs[d][r] = make_float2(v, v);
    }
    __syncthreads();

    const int cp = t & 63;
    const int rp4 = (t >> 6) * 4;

    const u64 NEG1 = 0xBF800000BF800000ULL;
    const u64 ABSM = 0x7FFFFFFF7FFFFFFFULL;

    u64 acc0 = 0, acc1 = 0, acc2 = 0, acc3 = 0;

    // y stream: pointer advanced by constant each body; loads at immediate offsets.
    const u64* yp = reinterpret_cast<const u64*>(zy) + (j0 >> 1) + cp;   // stride 512/d
    u64 yr[8];
    #pragma unroll
    for (int p = 0; p < 8; ++p) yr[p] = yp[(size_t)p * 512];

    // x stream: ulonglong2 view of xs; element index d*4 + rp4/2 (+1).
    const ulonglong2* xp = reinterpret_cast<const ulonglong2*>(xs) + (rp4 >> 1);

    auto body = [&](bool pf) {
        #pragma unroll
        for (int q = 0; q < 8; ++q) {
            u64 ycur = yr[q];
            if (pf) yr[q] = yp[(size_t)(q + 8) * 512];   // refill for next body
            ulonglong2 xa = xp[q * 4];                   // rows rp4, rp4+1 (dup pairs)
            ulonglong2 xb = xp[q * 4 + 1];               // rows rp4+2, rp4+3
            u64 t0, t1, t2, t3;
            FMA2(t0, ycur, NEG1, xa.x);
            FMA2(t1, ycur, NEG1, xa.y);
            FMA2(t2, ycur, NEG1, xb.x);
            FMA2(t3, ycur, NEG1, xb.y);
            t0 &= ABSM; t1 &= ABSM; t2 &= ABSM; t3 &= ABSM;
            ADD2(acc0, acc0, t0);
            ADD2(acc1, acc1, t1);
            ADD2(acc2, acc2, t2);
            ADD2(acc3, acc3, t3);
        }
        yp += 8 * 512;
        xp += 32;
    };

    for (int c = 0; c < Dd / 8 - 1; ++c) body(true);
    body(false);

    // Epilogue: store s = -dist, and per-4-row column partials (transposed).
    float sl[4], sh[4];
    sl[0] = -lo32(acc0); sh[0] = -hi32(acc0);
    sl[1] = -lo32(acc1); sh[1] = -hi32(acc1);
    sl[2] = -lo32(acc2); sh[2] = -hi32(acc2);
    sl[3] = -lo32(acc3); sh[3] = -hi32(acc3);

    const int ib = i0 + rp4;
    const int j = j0 + 2 * cp;
    #pragma unroll
    for (int r = 0; r < 4; ++r)
        *reinterpret_cast<float2*>(g_S + (size_t)(ib + r) * Mm + j) = make_float2(sl[r], sh[r]);

    float m0 = fmaxf(fmaxf(sl[0], sl[1]), fmaxf(sl[2], sl[3]));
    float m1 = fmaxf(fmaxf(sh[0], sh[1]), fmaxf(sh[2], sh[3]));
    float e0 = __expf(sl[0] - m0) + __expf(sl[1] - m0) + __expf(sl[2] - m0) + __expf(sl[3] - m0);
    float e1 = __expf(sh[0] - m1) + __expf(sh[1] - m1) + __expf(sh[2] - m1) + __expf(sh[3] - m1);

    const int g = rg * 2 + (rp4 >> 2);
    g_pm[(size_t)j * NGRP + g] = m0;
    g_pm[(size_t)(j + 1) * NGRP + g] = m1;
    g_ps[(size_t)j * NGRP + g] = e0;
    g_ps[(size_t)(j + 1) * NGRP + g] = e1;
}

// ===================== K2: combine 256 column partials (warp per column) =====================
__global__ __launch_bounds__(256) void k2_colcombine()
{
    const int w = threadIdx.x >> 5, lane = threadIdx.x & 31;
    const int j = blockIdx.x * 8 + w;
    const float4* pm = reinterpret_cast<const float4*>(g_pm + (size_t)j * NGRP);
    const float4* ps = reinterpret_cast<const float4*>(g_ps + (size_t)j * NGRP);

    float4 m4a = pm[lane * 2], m4b = pm[lane * 2 + 1];
    float m = fmaxf(fmaxf(fmaxf(m4a.x, m4a.y), fmaxf(m4a.z, m4a.w)),
                    fmaxf(fmaxf(m4b.x, m4b.y), fmaxf(m4b.z, m4b.w)));
    m = warpMax(m);

    float4 s4a = ps[lane * 2], s4b = ps[lane * 2 + 1];
    float s = s4a.x * __expf(m4a.x - m) + s4a.y * __expf(m4a.y - m) +
              s4a.z * __expf(m4a.z - m) + s4a.w * __expf(m4a.w - m) +
              s4b.x * __expf(m4b.x - m) + s4b.y * __expf(m4b.y - m) +
              s4b.z * __expf(m4b.z - m) + s4b.w * __expf(m4b.w - m);
    s = warpSum(s);

    if (lane == 0) { g_cm[j] = m; g_cinv[j] = 1.0f / s; }
}

// ===================== K3: warp-per-row final partials + last-block combine =====================
__global__ __launch_bounds__(256) void k3_rows(float* __restrict__ out)
{
    __shared__ float shn[8], shd[8];
    __shared__ u32 sh_last;
    const int t = threadIdx.x;
    const int w = t >> 5, lane = t & 31;
    const int i = blockIdx.x * 8 + w;
    const float4* row = reinterpret_cast<const float4*>(g_S + (size_t)i * Mm);

    float4 s[8];
    float m = -3.4e38f;
    #pragma unroll
    for (int q = 0; q < 8; ++q) {
        s[q] = row[q * 32 + lane];
        m = fmaxf(m, fmaxf(fmaxf(s[q].x, s[q].y), fmaxf(s[q].z, s[q].w)));
    }
    m = warpMax(m);

    float4 e[8];
    float rs = 0.f;
    #pragma unroll
    for (int q = 0; q < 8; ++q) {
        e[q].x = __expf(s[q].x - m); e[q].y = __expf(s[q].y - m);
        e[q].z = __expf(s[q].z - m); e[q].w = __expf(s[q].w - m);
        rs += e[q].x + e[q].y + e[q].z + e[q].w;
    }
    rs = warpSum(rs);
    const float rinv = 1.0f / rs;

    float num = 0.f, den = 0.f;
    #pragma unroll
    for (int q = 0; q < 8; ++q) {
        float4 cm = reinterpret_cast<const float4*>(g_cm)[q * 32 + lane];
        float4 ci = reinterpret_cast<const float4*>(g_cinv)[q * 32 + lane];
        {
            float a = e[q].x * rinv, b = __expf(s[q].x - cm.x) * ci.x;
            float u = a + b - a * b; num += u * s[q].x; den += u;
        }
        {
            float a = e[q].y * rinv, b = __expf(s[q].y - cm.y) * ci.y;
            float u = a + b - a * b; num += u * s[q].y; den += u;
        }
        {
            float a = e[q].z * rinv, b = __expf(s[q].z - cm.z) * ci.z;
            float u = a + b - a * b; num += u * s[q].z; den += u;
        }
        {
            float a = e[q].w * rinv, b = __expf(s[q].w - cm.w) * ci.w;
            float u = a + b - a * b; num += u * s[q].w; den += u;
        }
    }
    num = warpSum(num);
    den = warpSum(den);
    if (lane == 0) { g_num[i] = num; g_den[i] = den; }

    // ---- last-block deterministic combine ----
    __threadfence();
    __syncthreads();
    if (t == 0) sh_last = atomicAdd(&g_done, 1u);
    __syncthreads();
    if (sh_last != K3_BLOCKS - 1) return;

    __threadfence();   // acquire side: see all blocks' g_num/g_den
    float n2 = 0.f, d2 = 0.f;
    #pragma unroll
    for (int p = t; p < Nn; p += 256) { n2 += g_num[p]; d2 += g_den[p]; }
    n2 = warpSum(n2); d2 = warpSum(d2);
    if (lane == 0) { shn[w] = n2; shd[w] = d2; }
    __syncthreads();
    if (w == 0) {
        float n = (lane < 8) ? shn[lane] : 0.f;
        float d = (lane < 8) ? shd[lane] : 0.f;
        n = warpSum(n); d = warpSum(d);
        if (lane == 0) {
            out[0] = n / d;
            g_done = 0;          // self-reset for next graph replay
        }
    }
}

extern "C" void kernel_launch(void* const* d_in, const int* in_sizes, int n_in,
                              void* d_out, int out_size)
{
    const float* zx = (const float*)d_in[0];
    const float* zy = (const float*)d_in[1];
    float* out = (float*)d_out;

    k1_scores<<<(Nn / RG) * (Mm / CT), 128>>>(zx, zy);
    k2_colcombine<<<Mm / 8, 256>>>();
    k3_rows<<<K3_BLOCKS, 256>>>(out);
}

// round 10
// speedup vs baseline: 1.1925x; 1.1925x over previous
#include <cuda_runtime.h>
#include <cuda_fp16.h>

#define Dd 256
#define Nn 1024
#define Mm 1024
#define RG 8                  // rows per K1 tile
#define CT 128                // cols per K1 tile
#define NGRP 256              // 4-row column-partial groups (1024/4)
#define K3_BLOCKS 128

typedef unsigned long long u64;
typedef unsigned int u32;

// Scratch (static __device__ — no runtime allocation)
__device__ __half g_y16[Dd * Mm];         // fp16 copy of z_y (512 KB)
__device__ float g_S[Nn * Mm];            // score matrix s = -L1dist (4 MB)
__device__ float g_pm[Mm * NGRP];         // col partial max, transposed [col][group]
__device__ float g_ps[Mm * NGRP];         // col partial expsum
__device__ float g_cm[Mm], g_cinv[Mm];    // column max, 1/colsum
__device__ float g_num[Nn], g_den[Nn];    // per-row final partials
__device__ u32 g_done = 0;                // k3 last-block counter (self-resetting)

__device__ __forceinline__ float warpMax(float v) {
    #pragma unroll
    for (int o = 16; o; o >>= 1) v = fmaxf(v, __shfl_xor_sync(0xffffffffu, v, o));
    return v;
}
__device__ __forceinline__ float warpSum(float v) {
    #pragma unroll
    for (int o = 16; o; o >>= 1) v += __shfl_xor_sync(0xffffffffu, v, o);
    return v;
}

// ===================== K0: quantize z_y to fp16 =====================
__global__ __launch_bounds__(512) void k0_quant(const float* __restrict__ zy)
{
    const int i = blockIdx.x * 512 + threadIdx.x;       // grid covers 256K elems
    g_y16[i] = __float2half(zy[i]);
}

// ===================== K1: fp16 scores + per-4-row-group column partials =====================
// 1024 blocks (128 row-groups x 8 col-tiles), 128 threads.
// Thread t: col pair cp = t&63 (cols j0+2cp, j0+2cp+1), rows rp4..rp4+3.
// Mainloop: HSUB2 (diff, 2 cols) + habs2 + HADD2 (fp16 partial), fp32 upconvert every 8 d.
__global__ __launch_bounds__(128, 8) void k1_scores(
    const float* __restrict__ zx)
{
    __shared__ __align__(16) __half2 xs[Dd][RG];   // duplicated (x,x) fp16 pairs, 8KB
    const int t = threadIdx.x;
    const int rg = blockIdx.x >> 3;
    const int ct = blockIdx.x & 7;
    const int i0 = rg * RG, j0 = ct * CT;

    for (int idx = t; idx < Dd * RG; idx += 128) {
        int d = idx >> 3, r = idx & 7;
        __half h = __float2half(zx[d * Nn + i0 + r]);
        xs[d][r] = __half2half2(h);
    }
    __syncthreads();

    const int cp = t & 63;
    const int rp4 = (t >> 6) * 4;

    float2 facc[4];
    #pragma unroll
    for (int r = 0; r < 4; ++r) facc[r] = make_float2(0.f, 0.f);

    // y stream: half2 per lane per d; stride 512 half2 per d. Depth-8 register prefetch.
    const u32* yb = reinterpret_cast<const u32*>(g_y16) + (j0 >> 1) + cp;
    u32 yr[8];
    #pragma unroll
    for (int p = 0; p < 8; ++p) yr[p] = yb[(size_t)p * 512];

    // x stream: 4 half2 rows per d for this thread (one LDS.128).
    const uint2* xp = reinterpret_cast<const uint2*>(xs) + (rp4 >> 1);   // 8B units

    #define CHUNK(pf)                                                         \
    {                                                                         \
        __half2 p0 = __float2half2_rn(0.f), p1 = p0, p2 = p0, p3 = p0;        \
        _Pragma("unroll")                                                     \
        for (int q = 0; q < 8; ++q) {                                         \
            u32 ycur = yr[q];                                                 \
            if (pf) yr[q] = yb[(size_t)(q + 8) * 512];                        \
            __half2 y2 = *reinterpret_cast<__half2*>(&ycur);                  \
            uint4 xv = *reinterpret_cast<const uint4*>(xp + q * 4);           \
            __half2 x0 = *reinterpret_cast<__half2*>(&xv.x);                  \
            __half2 x1 = *reinterpret_cast<__half2*>(&xv.y);                  \
            __half2 x2 = *reinterpret_cast<__half2*>(&xv.z);                  \
            __half2 x3 = *reinterpret_cast<__half2*>(&xv.w);                  \
            p0 = __hadd2(p0, __habs2(__hsub2(x0, y2)));                       \
            p1 = __hadd2(p1, __habs2(__hsub2(x1, y2)));                       \
            p2 = __hadd2(p2, __habs2(__hsub2(x2, y2)));                       \
            p3 = __hadd2(p3, __habs2(__hsub2(x3, y2)));                       \
        }                                                                     \
        float2 f0 = __half22float2(p0), f1 = __half22float2(p1);              \
        float2 f2 = __half22float2(p2), f3 = __half22float2(p3);              \
        facc[0].x += f0.x; facc[0].y += f0.y;                                 \
        facc[1].x += f1.x; facc[1].y += f1.y;                                 \
        facc[2].x += f2.x; facc[2].y += f2.y;                                 \
        facc[3].x += f3.x; facc[3].y += f3.y;                                 \
        yb += 8 * 512;                                                        \
        xp += 32;                                                             \
    }

    for (int c = 0; c < Dd / 8 - 1; ++c) CHUNK(true);
    CHUNK(false);
    #undef CHUNK

    // Epilogue: store s = -dist, and per-4-row column partials (transposed).
    float sl[4], sh[4];
    #pragma unroll
    for (int r = 0; r < 4; ++r) { sl[r] = -facc[r].x; sh[r] = -facc[r].y; }

    const int ib = i0 + rp4;
    const int j = j0 + 2 * cp;
    #pragma unroll
    for (int r = 0; r < 4; ++r)
        *reinterpret_cast<float2*>(g_S + (size_t)(ib + r) * Mm + j) = make_float2(sl[r], sh[r]);

    float m0 = fmaxf(fmaxf(sl[0], sl[1]), fmaxf(sl[2], sl[3]));
    float m1 = fmaxf(fmaxf(sh[0], sh[1]), fmaxf(sh[2], sh[3]));
    float e0 = __expf(sl[0] - m0) + __expf(sl[1] - m0) + __expf(sl[2] - m0) + __expf(sl[3] - m0);
    float e1 = __expf(sh[0] - m1) + __expf(sh[1] - m1) + __expf(sh[2] - m1) + __expf(sh[3] - m1);

    const int g = rg * 2 + (rp4 >> 2);
    g_pm[(size_t)j * NGRP + g] = m0;
    g_pm[(size_t)(j + 1) * NGRP + g] = m1;
    g_ps[(size_t)j * NGRP + g] = e0;
    g_ps[(size_t)(j + 1) * NGRP + g] = e1;
}

// ===================== K2: combine 256 column partials (warp per column) =====================
__global__ __launch_bounds__(256) void k2_colcombine()
{
    const int w = threadIdx.x >> 5, lane = threadIdx.x & 31;
    const int j = blockIdx.x * 8 + w;
    const float4* pm = reinterpret_cast<const float4*>(g_pm + (size_t)j * NGRP);
    const float4* ps = reinterpret_cast<const float4*>(g_ps + (size_t)j * NGRP);

    float4 m4a = pm[lane * 2], m4b = pm[lane * 2 + 1];
    float m = fmaxf(fmaxf(fmaxf(m4a.x, m4a.y), fmaxf(m4a.z, m4a.w)),
                    fmaxf(fmaxf(m4b.x, m4b.y), fmaxf(m4b.z, m4b.w)));
    m = warpMax(m);

    float4 s4a = ps[lane * 2], s4b = ps[lane * 2 + 1];
    float s = s4a.x * __expf(m4a.x - m) + s4a.y * __expf(m4a.y - m) +
              s4a.z * __expf(m4a.z - m) + s4a.w * __expf(m4a.w - m) +
              s4b.x * __expf(m4b.x - m) + s4b.y * __expf(m4b.y - m) +
              s4b.z * __expf(m4b.z - m) + s4b.w * __expf(m4b.w - m);
    s = warpSum(s);

    if (lane == 0) { g_cm[j] = m; g_cinv[j] = 1.0f / s; }
}

// ===================== K3: warp-per-row final partials + last-block combine =====================
__global__ __launch_bounds__(256) void k3_rows(float* __restrict__ out)
{
    __shared__ float shn[8], shd[8];
    __shared__ u32 sh_last;
    const int t = threadIdx.x;
    const int w = t >> 5, lane = t & 31;
    const int i = blockIdx.x * 8 + w;
    const float4* row = reinterpret_cast<const float4*>(g_S + (size_t)i * Mm);

    float4 s[8];
    float m = -3.4e38f;
    #pragma unroll
    for (int q = 0; q < 8; ++q) {
        s[q] = row[q * 32 + lane];
        m = fmaxf(m, fmaxf(fmaxf(s[q].x, s[q].y), fmaxf(s[q].z, s[q].w)));
    }
    m = warpMax(m);

    float4 e[8];
    float rs = 0.f;
    #pragma unroll
    for (int q = 0; q < 8; ++q) {
        e[q].x = __expf(s[q].x - m); e[q].y = __expf(s[q].y - m);
        e[q].z = __expf(s[q].z - m); e[q].w = __expf(s[q].w - m);
        rs += e[q].x + e[q].y + e[q].z + e[q].w;
    }
    rs = warpSum(rs);
    const float rinv = 1.0f / rs;

    float num = 0.f, den = 0.f;
    #pragma unroll
    for (int q = 0; q < 8; ++q) {
        float4 cm = reinterpret_cast<const float4*>(g_cm)[q * 32 + lane];
        float4 ci = reinterpret_cast<const float4*>(g_cinv)[q * 32 + lane];
        {
            float a = e[q].x * rinv, b = __expf(s[q].x - cm.x) * ci.x;
            float u = a + b - a * b; num += u * s[q].x; den += u;
        }
        {
            float a = e[q].y * rinv, b = __expf(s[q].y - cm.y) * ci.y;
            float u = a + b - a * b; num += u * s[q].y; den += u;
        }
        {
            float a = e[q].z * rinv, b = __expf(s[q].z - cm.z) * ci.z;
            float u = a + b - a * b; num += u * s[q].z; den += u;
        }
        {
            float a = e[q].w * rinv, b = __expf(s[q].w - cm.w) * ci.w;
            float u = a + b - a * b; num += u * s[q].w; den += u;
        }
    }
    num = warpSum(num);
    den = warpSum(den);
    if (lane == 0) { g_num[i] = num; g_den[i] = den; }

    // ---- last-block deterministic combine ----
    __threadfence();
    __syncthreads();
    if (t == 0) sh_last = atomicAdd(&g_done, 1u);
    __syncthreads();
    if (sh_last != K3_BLOCKS - 1) return;

    __threadfence();   // acquire side: see all blocks' g_num/g_den
    float n2 = 0.f, d2 = 0.f;
    #pragma unroll
    for (int p = t; p < Nn; p += 256) { n2 += g_num[p]; d2 += g_den[p]; }
    n2 = warpSum(n2); d2 = warpSum(d2);
    if (lane == 0) { shn[w] = n2; shd[w] = d2; }
    __syncthreads();
    if (w == 0) {
        float n = (lane < 8) ? shn[lane] : 0.f;
        float d = (lane < 8) ? shd[lane] : 0.f;
        n = warpSum(n); d = warpSum(d);
        if (lane == 0) {
            out[0] = n / d;
            g_done = 0;          // self-reset for next graph replay
        }
    }
}

extern "C" void kernel_launch(void* const* d_in, const int* in_sizes, int n_in,
                              void* d_out, int out_size)
{
    const float* zx = (const float*)d_in[0];
    const float* zy = (const float*)d_in[1];
    float* out = (float*)d_out;

    k0_quant<<<(Dd * Mm) / 512, 512>>>(zy);
    k1_scores<<<(Nn / RG) * (Mm / CT), 128>>>(zx);
    k2_colcombine<<<Mm / 8, 256>>>();
    k3_rows<<<K3_BLOCKS, 256>>>(out);
}

// round 11
// speedup vs baseline: 1.2158x; 1.0195x over previous
#include <cuda_runtime.h>
#include <cuda_fp16.h>

#define Dd 256
#define Nn 1024
#define Mm 1024
#define RG 8                  // rows per K1 tile
#define CT 128                // cols per K1 tile
#define NGRP 128              // 8-row column-partial groups (1024/8)
#define K3_BLOCKS 1024

typedef unsigned long long u64;
typedef unsigned int u32;

// Scratch (static __device__ — no runtime allocation)
__device__ __half g_y16[Dd * Mm];         // fp16 copy of z_y (512 KB)
__device__ float g_S[Nn * Mm];            // score matrix s = -L1dist (4 MB)
__device__ float g_pm[Mm * NGRP];         // col partial max, transposed [col][group]
__device__ float g_ps[Mm * NGRP];         // col partial expsum
__device__ float g_rpm[Nn * 8];           // row partial max [row][colgroup]
__device__ float g_rps[Nn * 8];           // row partial expsum
__device__ float g_cm[Mm], g_cinv[Mm];    // column max, 1/colsum
__device__ float g_rm[Nn], g_rinv[Nn];    // row max, 1/rowsum
__device__ float g_num[K3_BLOCKS], g_den[K3_BLOCKS];
__device__ u32 g_done = 0;                // k3 last-block counter (self-resetting)

__device__ __forceinline__ float warpMax(float v) {
    #pragma unroll
    for (int o = 16; o; o >>= 1) v = fmaxf(v, __shfl_xor_sync(0xffffffffu, v, o));
    return v;
}
__device__ __forceinline__ float warpSum(float v) {
    #pragma unroll
    for (int o = 16; o; o >>= 1) v += __shfl_xor_sync(0xffffffffu, v, o);
    return v;
}

// ===================== K0: quantize z_y to fp16 =====================
__global__ __launch_bounds__(512) void k0_quant(const float* __restrict__ zy)
{
    const int i = blockIdx.x * 512 + threadIdx.x;       // grid covers 256K elems
    g_y16[i] = __float2half(zy[i]);
}

// ===================== K1: fp16 scores + col partials (8-row) + row partials (128-col) ====
// 1024 blocks (128 row-groups x 8 col-tiles), 128 threads.
// Thread t: col pair cp = t&63 (cols j0+2cp, j0+2cp+1), rows rp4..rp4+3.
// Mainloop: HSUB2 (diff, 2 cols) + habs2 + HADD2 (fp16 partial), fp32 upconvert every 8 d.
__global__ __launch_bounds__(128, 8) void k1_scores(
    const float* __restrict__ zx)
{
    __shared__ __align__(16) __half2 xs[Dd][RG];   // duplicated (x,x) fp16 pairs, 8KB
    __shared__ __align__(16) float sbuf[RG][CT];   // epilogue transpose buffer, 4KB
    const int t = threadIdx.x;
    const int w = t >> 5, lane = t & 31;
    const int rg = blockIdx.x >> 3;
    const int ct = blockIdx.x & 7;
    const int i0 = rg * RG, j0 = ct * CT;

    for (int idx = t; idx < Dd * RG; idx += 128) {
        int d = idx >> 3, r = idx & 7;
        __half h = __float2half(zx[d * Nn + i0 + r]);
        xs[d][r] = __half2half2(h);
    }
    __syncthreads();

    const int cp = t & 63;
    const int rp4 = (t >> 6) * 4;

    float2 facc[4];
    #pragma unroll
    for (int r = 0; r < 4; ++r) facc[r] = make_float2(0.f, 0.f);

    // y stream: half2 per lane per d; stride 512 half2 per d. Depth-8 register prefetch.
    const u32* yb = reinterpret_cast<const u32*>(g_y16) + (j0 >> 1) + cp;
    u32 yr[8];
    #pragma unroll
    for (int p = 0; p < 8; ++p) yr[p] = yb[(size_t)p * 512];

    // x stream: 4 half2 rows per d for this thread (one LDS.128).
    const uint2* xp = reinterpret_cast<const uint2*>(xs) + (rp4 >> 1);   // 8B units

    #define CHUNK(pf)                                                         \
    {                                                                         \
        __half2 p0 = __float2half2_rn(0.f), p1 = p0, p2 = p0, p3 = p0;        \
        _Pragma("unroll")                                                     \
        for (int q = 0; q < 8; ++q) {                                         \
            u32 ycur = yr[q];                                                 \
            if (pf) yr[q] = yb[(size_t)(q + 8) * 512];                        \
            __half2 y2 = *reinterpret_cast<__half2*>(&ycur);                  \
            uint4 xv = *reinterpret_cast<const uint4*>(xp + q * 4);           \
            __half2 x0 = *reinterpret_cast<__half2*>(&xv.x);                  \
            __half2 x1 = *reinterpret_cast<__half2*>(&xv.y);                  \
            __half2 x2 = *reinterpret_cast<__half2*>(&xv.z);                  \
            __half2 x3 = *reinterpret_cast<__half2*>(&xv.w);                  \
            p0 = __hadd2(p0, __habs2(__hsub2(x0, y2)));                       \
            p1 = __hadd2(p1, __habs2(__hsub2(x1, y2)));                       \
            p2 = __hadd2(p2, __habs2(__hsub2(x2, y2)));                       \
            p3 = __hadd2(p3, __habs2(__hsub2(x3, y2)));                       \
        }                                                                     \
        float2 f0 = __half22float2(p0), f1 = __half22float2(p1);              \
        float2 f2 = __half22float2(p2), f3 = __half22float2(p3);              \
        facc[0].x += f0.x; facc[0].y += f0.y;                                 \
        facc[1].x += f1.x; facc[1].y += f1.y;                                 \
        facc[2].x += f2.x; facc[2].y += f2.y;                                 \
        facc[3].x += f3.x; facc[3].y += f3.y;                                 \
        yb += 8 * 512;                                                        \
        xp += 32;                                                             \
    }

    for (int c = 0; c < Dd / 8 - 1; ++c) CHUNK(true);
    CHUNK(false);
    #undef CHUNK

    // Epilogue: store s = -dist to gmem + smem transpose buffer.
    float sl[4], sh[4];
    #pragma unroll
    for (int r = 0; r < 4; ++r) { sl[r] = -facc[r].x; sh[r] = -facc[r].y; }

    const int ib = i0 + rp4;
    const int j = j0 + 2 * cp;
    #pragma unroll
    for (int r = 0; r < 4; ++r) {
        *reinterpret_cast<float2*>(g_S + (size_t)(ib + r) * Mm + j) = make_float2(sl[r], sh[r]);
        *reinterpret_cast<float2*>(&sbuf[rp4 + r][2 * cp]) = make_float2(sl[r], sh[r]);
    }
    __syncthreads();

    // Column partials over this block's 8 rows (thread per column).
    {
        const int c = t;                       // column j0+c
        float v0 = sbuf[0][c], v1 = sbuf[1][c], v2 = sbuf[2][c], v3 = sbuf[3][c];
        float v4 = sbuf[4][c], v5 = sbuf[5][c], v6 = sbuf[6][c], v7 = sbuf[7][c];
        float m = fmaxf(fmaxf(fmaxf(v0, v1), fmaxf(v2, v3)),
                        fmaxf(fmaxf(v4, v5), fmaxf(v6, v7)));
        float e = __expf(v0 - m) + __expf(v1 - m) + __expf(v2 - m) + __expf(v3 - m) +
                  __expf(v4 - m) + __expf(v5 - m) + __expf(v6 - m) + __expf(v7 - m);
        g_pm[(size_t)(j0 + c) * NGRP + rg] = m;
        g_ps[(size_t)(j0 + c) * NGRP + rg] = e;
    }

    // Row partials over this block's 128 cols (warp w handles rows 2w, 2w+1).
    #pragma unroll
    for (int rr = 2 * w; rr < 2 * w + 2; ++rr) {
        float a0 = sbuf[rr][lane],      a1 = sbuf[rr][lane + 32];
        float a2 = sbuf[rr][lane + 64], a3 = sbuf[rr][lane + 96];
        float lm = fmaxf(fmaxf(a0, a1), fmaxf(a2, a3));
        lm = warpMax(lm);
        float le = __expf(a0 - lm) + __expf(a1 - lm) + __expf(a2 - lm) + __expf(a3 - lm);
        le = warpSum(le);
        if (lane == 0) {
            g_rpm[(size_t)(i0 + rr) * 8 + ct] = lm;
            g_rps[(size_t)(i0 + rr) * 8 + ct] = le;
        }
    }
}

// ===================== K2: combine partials (cols: blocks 0..127; rows: 128..131) ========
__global__ __launch_bounds__(256) void k2_combine()
{
    const int bid = blockIdx.x;
    if (bid < 128) {
        // warp per column, 128 partials each
        const int w = threadIdx.x >> 5, lane = threadIdx.x & 31;
        const int j = bid * 8 + w;
        const float4 m4 = reinterpret_cast<const float4*>(g_pm + (size_t)j * NGRP)[lane];
        const float4 s4 = reinterpret_cast<const float4*>(g_ps + (size_t)j * NGRP)[lane];

        float m = fmaxf(fmaxf(m4.x, m4.y), fmaxf(m4.z, m4.w));
        m = warpMax(m);
        float s = s4.x * __expf(m4.x - m) + s4.y * __expf(m4.y - m) +
                  s4.z * __expf(m4.z - m) + s4.w * __expf(m4.w - m);
        s = warpSum(s);
        if (lane == 0) { g_cm[j] = m; g_cinv[j] = 1.0f / s; }
    } else {
        // thread per row, 8 partials each
        const int i = (bid - 128) * 256 + threadIdx.x;
        float4 ma = reinterpret_cast<const float4*>(g_rpm + (size_t)i * 8)[0];
        float4 mb = reinterpret_cast<const float4*>(g_rpm + (size_t)i * 8)[1];
        float4 sa = reinterpret_cast<const float4*>(g_rps + (size_t)i * 8)[0];
        float4 sb = reinterpret_cast<const float4*>(g_rps + (size_t)i * 8)[1];
        float m = fmaxf(fmaxf(fmaxf(ma.x, ma.y), fmaxf(ma.z, ma.w)),
                        fmaxf(fmaxf(mb.x, mb.y), fmaxf(mb.z, mb.w)));
        float s = sa.x * __expf(ma.x - m) + sa.y * __expf(ma.y - m) +
                  sa.z * __expf(ma.z - m) + sa.w * __expf(ma.w - m) +
                  sb.x * __expf(mb.x - m) + sb.y * __expf(mb.y - m) +
                  sb.z * __expf(mb.z - m) + sb.w * __expf(mb.w - m);
        g_rm[i] = m;
        g_rinv[i] = 1.0f / s;
    }
}

// ===================== K3: single-pass elementwise + last-block combine =====================
// 1024 blocks (row per block), 256 threads (thread = 4 cols).
__global__ __launch_bounds__(256) void k3_final(float* __restrict__ out)
{
    __shared__ float shn[8], shd[8];
    __shared__ u32 sh_last;
    const int t = threadIdx.x;
    const int w = t >> 5, lane = t & 31;
    const int i = blockIdx.x;

    const float rm = g_rm[i];
    const float rinv = g_rinv[i];
    const float4 s4 = reinterpret_cast<const float4*>(g_S + (size_t)i * Mm)[t];
    const float4 cm = reinterpret_cast<const float4*>(g_cm)[t];
    const float4 ci = reinterpret_cast<const float4*>(g_cinv)[t];

    float num = 0.f, den = 0.f;
    {
        float a = __expf(s4.x - rm) * rinv, b = __expf(s4.x - cm.x) * ci.x;
        float u = a + b - a * b; num += u * s4.x; den += u;
    }
    {
        float a = __expf(s4.y - rm) * rinv, b = __expf(s4.y - cm.y) * ci.y;
        float u = a + b - a * b; num += u * s4.y; den += u;
    }
    {
        float a = __expf(s4.z - rm) * rinv, b = __expf(s4.z - cm.z) * ci.z;
        float u = a + b - a * b; num += u * s4.z; den += u;
    }
    {
        float a = __expf(s4.w - rm) * rinv, b = __expf(s4.w - cm.w) * ci.w;
        float u = a + b - a * b; num += u * s4.w; den += u;
    }

    num = warpSum(num); den = warpSum(den);
    if (lane == 0) { shn[w] = num; shd[w] = den; }
    __syncthreads();
    if (w == 0) {
        float n = (lane < 8) ? shn[lane] : 0.f;
        float d = (lane < 8) ? shd[lane] : 0.f;
        n = warpSum(n); d = warpSum(d);
        if (lane == 0) { g_num[i] = n; g_den[i] = d; }
    }

    // ---- last-block deterministic combine ----
    __threadfence();
    __syncthreads();
    if (t == 0) sh_last = atomicAdd(&g_done, 1u);
    __syncthreads();
    if (sh_last != K3_BLOCKS - 1) return;

    __threadfence();   // acquire side: see all blocks' g_num/g_den
    float n2 = 0.f, d2 = 0.f;
    #pragma unroll
    for (int p = t; p < K3_BLOCKS; p += 256) { n2 += g_num[p]; d2 += g_den[p]; }
    n2 = warpSum(n2); d2 = warpSum(d2);
    if (lane == 0) { shn[w] = n2; shd[w] = d2; }
    __syncthreads();
    if (w == 0) {
        float n = (lane < 8) ? shn[lane] : 0.f;
        float d = (lane < 8) ? shd[lane] : 0.f;
        n = warpSum(n); d = warpSum(d);
        if (lane == 0) {
            out[0] = n / d;
            g_done = 0;          // self-reset for next graph replay
        }
    }
}

extern "C" void kernel_launch(void* const* d_in, const int* in_sizes, int n_in,
                              void* d_out, int out_size)
{
    const float* zx = (const float*)d_in[0];
    const float* zy = (const float*)d_in[1];
    float* out = (float*)d_out;

    k0_quant<<<(Dd * Mm) / 512, 512>>>(zy);
    k1_scores<<<(Nn / RG) * (Mm / CT), 128>>>(zx);
    k2_combine<<<132, 256>>>();
    k3_final<<<K3_BLOCKS, 256>>>(out);
}

// round 12
// speedup vs baseline: 1.2252x; 1.0077x over previous
#include <cuda_runtime.h>
#include <cuda_fp16.h>

#define Dd 256
#define Nn 1024
#define Mm 1024
#define RG 8                  // rows per K1 tile
#define CT 128                // cols per K1 tile
#define NGRP 128              // 8-row column-partial groups (1024/8)
#define K3_BLOCKS 256

typedef unsigned long long u64;
typedef unsigned int u32;

// Scratch (static __device__ — no runtime allocation)
__device__ __half g_y16[Dd * Mm];         // fp16 copy of z_y (512 KB)
__device__ float g_S[Nn * Mm];            // score matrix s = -L1dist (4 MB)
__device__ float g_pm[Mm * NGRP];         // col partial max, transposed [col][group]
__device__ float g_ps[Mm * NGRP];         // col partial expsum
__device__ float g_rpm[Nn * 8];           // row partial max [row][colgroup]
__device__ float g_rps[Nn * 8];           // row partial expsum
__device__ float g_cm[Mm], g_cinv[Mm];    // column max, 1/colsum
__device__ float g_rm[Nn], g_rinv[Nn];    // row max, 1/rowsum
__device__ float g_num[K3_BLOCKS], g_den[K3_BLOCKS];
__device__ u32 g_done = 0;                // k3 last-block counter (self-resetting)

__device__ __forceinline__ float warpMax(float v) {
    #pragma unroll
    for (int o = 16; o; o >>= 1) v = fmaxf(v, __shfl_xor_sync(0xffffffffu, v, o));
    return v;
}
__device__ __forceinline__ float warpSum(float v) {
    #pragma unroll
    for (int o = 16; o; o >>= 1) v += __shfl_xor_sync(0xffffffffu, v, o);
    return v;
}

// ===================== K0: quantize z_y to fp16 =====================
__global__ __launch_bounds__(512) void k0_quant(const float* __restrict__ zy)
{
    const int i = blockIdx.x * 512 + threadIdx.x;       // grid covers 256K elems
    g_y16[i] = __float2half(zy[i]);
}

// ===================== K1: fp16 scores + col partials (8-row) + row partials (128-col) ====
// 1024 blocks (128 row-groups x 8 col-tiles), 128 threads.
// Thread t: col pair cp = t&63 (cols j0+2cp, j0+2cp+1), rows rp4..rp4+3.
// Mainloop: HSUB2 (diff, 2 cols) + habs2 + HADD2 (fp16 partial), fp32 upconvert every 8 d.
__global__ __launch_bounds__(128, 8) void k1_scores(
    const float* __restrict__ zx)
{
    __shared__ __align__(16) __half2 xs[Dd][RG];   // duplicated (x,x) fp16 pairs, 8KB
    __shared__ __align__(16) float sbuf[RG][CT];   // epilogue transpose buffer, 4KB
    const int t = threadIdx.x;
    const int w = t >> 5, lane = t & 31;
    const int rg = blockIdx.x >> 3;
    const int ct = blockIdx.x & 7;
    const int i0 = rg * RG, j0 = ct * CT;

    for (int idx = t; idx < Dd * RG; idx += 128) {
        int d = idx >> 3, r = idx & 7;
        __half h = __float2half(zx[d * Nn + i0 + r]);
        xs[d][r] = __half2half2(h);
    }
    __syncthreads();

    const int cp = t & 63;
    const int rp4 = (t >> 6) * 4;

    float2 facc[4];
    #pragma unroll
    for (int r = 0; r < 4; ++r) facc[r] = make_float2(0.f, 0.f);

    // y stream: half2 per lane per d; stride 512 half2 per d. Depth-8 register prefetch.
    const u32* yb = reinterpret_cast<const u32*>(g_y16) + (j0 >> 1) + cp;
    u32 yr[8];
    #pragma unroll
    for (int p = 0; p < 8; ++p) yr[p] = yb[(size_t)p * 512];

    // x stream: 4 half2 rows per d for this thread (one LDS.128).
    const uint2* xp = reinterpret_cast<const uint2*>(xs) + (rp4 >> 1);   // 8B units

    #define CHUNK(pf)                                                         \
    {                                                                         \
        __half2 p0 = __float2half2_rn(0.f), p1 = p0, p2 = p0, p3 = p0;        \
        _Pragma("unroll")                                                     \
        for (int q = 0; q < 8; ++q) {                                         \
            u32 ycur = yr[q];                                                 \
            if (pf) yr[q] = yb[(size_t)(q + 8) * 512];                        \
            __half2 y2 = *reinterpret_cast<__half2*>(&ycur);                  \
            uint4 xv = *reinterpret_cast<const uint4*>(xp + q * 4);           \
            __half2 x0 = *reinterpret_cast<__half2*>(&xv.x);                  \
            __half2 x1 = *reinterpret_cast<__half2*>(&xv.y);                  \
            __half2 x2 = *reinterpret_cast<__half2*>(&xv.z);                  \
            __half2 x3 = *reinterpret_cast<__half2*>(&xv.w);                  \
            p0 = __hadd2(p0, __habs2(__hsub2(x0, y2)));                       \
            p1 = __hadd2(p1, __habs2(__hsub2(x1, y2)));                       \
            p2 = __hadd2(p2, __habs2(__hsub2(x2, y2)));                       \
            p3 = __hadd2(p3, __habs2(__hsub2(x3, y2)));                       \
        }                                                                     \
        float2 f0 = __half22float2(p0), f1 = __half22float2(p1);              \
        float2 f2 = __half22float2(p2), f3 = __half22float2(p3);              \
        facc[0].x += f0.x; facc[0].y += f0.y;                                 \
        facc[1].x += f1.x; facc[1].y += f1.y;                                 \
        facc[2].x += f2.x; facc[2].y += f2.y;                                 \
        facc[3].x += f3.x; facc[3].y += f3.y;                                 \
        yb += 8 * 512;                                                        \
        xp += 32;                                                             \
    }

    for (int c = 0; c < Dd / 8 - 1; ++c) CHUNK(true);
    CHUNK(false);
    #undef CHUNK

    // Epilogue: store s = -dist to gmem + smem transpose buffer.
    float sl[4], sh[4];
    #pragma unroll
    for (int r = 0; r < 4; ++r) { sl[r] = -facc[r].x; sh[r] = -facc[r].y; }

    const int ib = i0 + rp4;
    const int j = j0 + 2 * cp;
    #pragma unroll
    for (int r = 0; r < 4; ++r) {
        *reinterpret_cast<float2*>(g_S + (size_t)(ib + r) * Mm + j) = make_float2(sl[r], sh[r]);
        *reinterpret_cast<float2*>(&sbuf[rp4 + r][2 * cp]) = make_float2(sl[r], sh[r]);
    }
    __syncthreads();

    // Column partials over this block's 8 rows (thread per column).
    {
        const int c = t;                       // column j0+c
        float v0 = sbuf[0][c], v1 = sbuf[1][c], v2 = sbuf[2][c], v3 = sbuf[3][c];
        float v4 = sbuf[4][c], v5 = sbuf[5][c], v6 = sbuf[6][c], v7 = sbuf[7][c];
        float m = fmaxf(fmaxf(fmaxf(v0, v1), fmaxf(v2, v3)),
                        fmaxf(fmaxf(v4, v5), fmaxf(v6, v7)));
        float e = __expf(v0 - m) + __expf(v1 - m) + __expf(v2 - m) + __expf(v3 - m) +
                  __expf(v4 - m) + __expf(v5 - m) + __expf(v6 - m) + __expf(v7 - m);
        g_pm[(size_t)(j0 + c) * NGRP + rg] = m;
        g_ps[(size_t)(j0 + c) * NGRP + rg] = e;
    }

    // Row partials over this block's 128 cols (warp w handles rows 2w, 2w+1).
    #pragma unroll
    for (int rr = 2 * w; rr < 2 * w + 2; ++rr) {
        float a0 = sbuf[rr][lane],      a1 = sbuf[rr][lane + 32];
        float a2 = sbuf[rr][lane + 64], a3 = sbuf[rr][lane + 96];
        float lm = fmaxf(fmaxf(a0, a1), fmaxf(a2, a3));
        lm = warpMax(lm);
        float le = __expf(a0 - lm) + __expf(a1 - lm) + __expf(a2 - lm) + __expf(a3 - lm);
        le = warpSum(le);
        if (lane == 0) {
            g_rpm[(size_t)(i0 + rr) * 8 + ct] = lm;
            g_rps[(size_t)(i0 + rr) * 8 + ct] = le;
        }
    }
}

// ===================== K2: combine partials (cols: blocks 0..127; rows: 128..131) ========
__global__ __launch_bounds__(256) void k2_combine()
{
    const int bid = blockIdx.x;
    if (bid < 128) {
        // warp per column, 128 partials each
        const int w = threadIdx.x >> 5, lane = threadIdx.x & 31;
        const int j = bid * 8 + w;
        const float4 m4 = reinterpret_cast<const float4*>(g_pm + (size_t)j * NGRP)[lane];
        const float4 s4 = reinterpret_cast<const float4*>(g_ps + (size_t)j * NGRP)[lane];

        float m = fmaxf(fmaxf(m4.x, m4.y), fmaxf(m4.z, m4.w));
        m = warpMax(m);
        float s = s4.x * __expf(m4.x - m) + s4.y * __expf(m4.y - m) +
                  s4.z * __expf(m4.z - m) + s4.w * __expf(m4.w - m);
        s = warpSum(s);
        if (lane == 0) { g_cm[j] = m; g_cinv[j] = 1.0f / s; }
    } else {
        // thread per row, 8 partials each
        const int i = (bid - 128) * 256 + threadIdx.x;
        float4 ma = reinterpret_cast<const float4*>(g_rpm + (size_t)i * 8)[0];
        float4 mb = reinterpret_cast<const float4*>(g_rpm + (size_t)i * 8)[1];
        float4 sa = reinterpret_cast<const float4*>(g_rps + (size_t)i * 8)[0];
        float4 sb = reinterpret_cast<const float4*>(g_rps + (size_t)i * 8)[1];
        float m = fmaxf(fmaxf(fmaxf(ma.x, ma.y), fmaxf(ma.z, ma.w)),
                        fmaxf(fmaxf(mb.x, mb.y), fmaxf(mb.z, mb.w)));
        float s = sa.x * __expf(ma.x - m) + sa.y * __expf(ma.y - m) +
                  sa.z * __expf(ma.z - m) + sa.w * __expf(ma.w - m) +
                  sb.x * __expf(mb.x - m) + sb.y * __expf(mb.y - m) +
                  sb.z * __expf(mb.z - m) + sb.w * __expf(mb.w - m);
        g_rm[i] = m;
        g_rinv[i] = 1.0f / s;
    }
}

// ===================== K3: high-MLP elementwise + last-block combine =====================
// 256 blocks x 256 threads. Block b owns rows 4b..4b+3; warp-pair per row.
// Thread: row r = 4b + (t>>6), 4 float4s at float4-cols (t&63) + 64q — 12 loads in flight.
__global__ __launch_bounds__(256) void k3_final(float* __restrict__ out)
{
    __shared__ float shn[8], shd[8];
    __shared__ u32 sh_last;
    const int t = threadIdx.x;
    const int w = t >> 5, lane = t & 31;
    const int r = blockIdx.x * 4 + (t >> 6);
    const int c0 = t & 63;                     // base float4-column

    const float rm = g_rm[r];
    const float rinv = g_rinv[r];
    const float4* Srow = reinterpret_cast<const float4*>(g_S + (size_t)r * Mm);
    const float4* CM = reinterpret_cast<const float4*>(g_cm);
    const float4* CI = reinterpret_cast<const float4*>(g_cinv);

    // Issue all 12 independent loads first (MLP=12).
    float4 s4[4], cm4[4], ci4[4];
    #pragma unroll
    for (int q = 0; q < 4; ++q) s4[q] = Srow[c0 + 64 * q];
    #pragma unroll
    for (int q = 0; q < 4; ++q) cm4[q] = CM[c0 + 64 * q];
    #pragma unroll
    for (int q = 0; q < 4; ++q) ci4[q] = CI[c0 + 64 * q];

    float num = 0.f, den = 0.f;
    #pragma unroll
    for (int q = 0; q < 4; ++q) {
        {
            float a = __expf(s4[q].x - rm) * rinv, b = __expf(s4[q].x - cm4[q].x) * ci4[q].x;
            float u = a + b - a * b; num += u * s4[q].x; den += u;
        }
        {
            float a = __expf(s4[q].y - rm) * rinv, b = __expf(s4[q].y - cm4[q].y) * ci4[q].y;
            float u = a + b - a * b; num += u * s4[q].y; den += u;
        }
        {
            float a = __expf(s4[q].z - rm) * rinv, b = __expf(s4[q].z - cm4[q].z) * ci4[q].z;
            float u = a + b - a * b; num += u * s4[q].z; den += u;
        }
        {
            float a = __expf(s4[q].w - rm) * rinv, b = __expf(s4[q].w - cm4[q].w) * ci4[q].w;
            float u = a + b - a * b; num += u * s4[q].w; den += u;
        }
    }

    num = warpSum(num); den = warpSum(den);
    if (lane == 0) { shn[w] = num; shd[w] = den; }
    __syncthreads();
    if (w == 0) {
        float n = (lane < 8) ? shn[lane] : 0.f;
        float d = (lane < 8) ? shd[lane] : 0.f;
        n = warpSum(n); d = warpSum(d);
        if (lane == 0) { g_num[blockIdx.x] = n; g_den[blockIdx.x] = d; }
    }

    // ---- last-block deterministic combine ----
    __threadfence();
    __syncthreads();
    if (t == 0) sh_last = atomicAdd(&g_done, 1u);
    __syncthreads();
    if (sh_last != K3_BLOCKS - 1) return;

    __threadfence();   // acquire side: see all blocks' g_num/g_den
    float n2 = (t < K3_BLOCKS) ? g_num[t] : 0.f;
    float d2 = (t < K3_BLOCKS) ? g_den[t] : 0.f;
    n2 = warpSum(n2); d2 = warpSum(d2);
    if (lane == 0) { shn[w] = n2; shd[w] = d2; }
    __syncthreads();
    if (w == 0) {
        float n = (lane < 8) ? shn[lane] : 0.f;
        float d = (lane < 8) ? shd[lane] : 0.f;
        n = warpSum(n); d = warpSum(d);
        if (lane == 0) {
            out[0] = n / d;
            g_done = 0;          // self-reset for next graph replay
        }
    }
}

extern "C" void kernel_launch(void* const* d_in, const int* in_sizes, int n_in,
                              void* d_out, int out_size)
{
    const float* zx = (const float*)d_in[0];
    const float* zy = (const float*)d_in[1];
    float* out = (float*)d_out;

    k0_quant<<<(Dd * Mm) / 512, 512>>>(zy);
    k1_scores<<<(Nn / RG) * (Mm / CT), 128>>>(zx);
    k2_combine<<<132, 256>>>();
    k3_final<<<K3_BLOCKS, 256>>>(out);
}

// round 13
// speedup vs baseline: 1.2262x; 1.0009x over previous
#include <cuda_runtime.h>
#include <cuda_fp16.h>

#define Dd 256
#define Nn 1024
#define Mm 1024
#define RG 8                  // rows per K1 tile
#define CT 128                // cols per K1 tile
#define NGRP 128              // 8-row column-partial groups (1024/8)
#define K3_BLOCKS 256

typedef unsigned long long u64;
typedef unsigned int u32;

// Scratch (static __device__ — no runtime allocation)
__device__ __half g_y16[Dd * Mm];         // fp16 copy of z_y (512 KB)
__device__ float g_S[Nn * Mm];            // score matrix s = -L1dist (4 MB)
__device__ float g_pm[Mm * NGRP];         // col partial max, transposed [col][group]
__device__ float g_ps[Mm * NGRP];         // col partial expsum
__device__ float g_rpm[Nn * 8];           // row partial max [row][colgroup]
__device__ float g_rps[Nn * 8];           // row partial expsum
__device__ float g_cm[Mm], g_cinv[Mm];    // column max, 1/colsum
__device__ float g_rm[Nn], g_rinv[Nn];    // row max, 1/rowsum
__device__ float g_num[K3_BLOCKS], g_den[K3_BLOCKS];
__device__ u32 g_done = 0;                // k3 last-block counter (self-resetting)

__device__ __forceinline__ float warpMax(float v) {
    #pragma unroll
    for (int o = 16; o; o >>= 1) v = fmaxf(v, __shfl_xor_sync(0xffffffffu, v, o));
    return v;
}
__device__ __forceinline__ float warpSum(float v) {
    #pragma unroll
    for (int o = 16; o; o >>= 1) v += __shfl_xor_sync(0xffffffffu, v, o);
    return v;
}

// abs of both fp16 halves as an integer AND — LOP3 on the ALU pipe,
// keeping HSUB2/HADD2 as the only fma-pipe ops in the mainloop.
__device__ __forceinline__ __half2 h2abs_alu(__half2 v) {
    u32 u = *reinterpret_cast<u32*>(&v);
    u &= 0x7FFF7FFFu;
    return *reinterpret_cast<__half2*>(&u);
}

// ===================== K0: quantize z_y to fp16 =====================
__global__ __launch_bounds__(512) void k0_quant(const float* __restrict__ zy)
{
    const int i = blockIdx.x * 512 + threadIdx.x;       // grid covers 256K elems
    g_y16[i] = __float2half(zy[i]);
}

// ===================== K1: fp16 scores + col partials (8-row) + row partials (128-col) ====
// 1024 blocks (128 row-groups x 8 col-tiles), 128 threads.
// Thread t: col pair cp = t&63 (cols j0+2cp, j0+2cp+1), rows rp4..rp4+3.
// Mainloop: HSUB2 (fma) + AND-abs (alu) + HADD2 (fma); fp16 partials over 16 d,
// fp32 upconvert per 16-d chunk. Depth-8 y register prefetch.
__global__ __launch_bounds__(128, 8) void k1_scores(
    const float* __restrict__ zx)
{
    __shared__ __align__(16) __half2 xs[Dd][RG];   // duplicated (x,x) fp16 pairs, 8KB
    __shared__ __align__(16) float sbuf[RG][CT];   // epilogue transpose buffer, 4KB
    const int t = threadIdx.x;
    const int w = t >> 5, lane = t & 31;
    const int rg = blockIdx.x >> 3;
    const int ct = blockIdx.x & 7;
    const int i0 = rg * RG, j0 = ct * CT;

    for (int idx = t; idx < Dd * RG; idx += 128) {
        int d = idx >> 3, r = idx & 7;
        __half h = __float2half(zx[d * Nn + i0 + r]);
        xs[d][r] = __half2half2(h);
    }
    __syncthreads();

    const int cp = t & 63;
    const int rp4 = (t >> 6) * 4;

    float2 facc[4];
    #pragma unroll
    for (int r = 0; r < 4; ++r) facc[r] = make_float2(0.f, 0.f);

    // y stream: half2 per lane per d; stride 512 half2 per d. Depth-8 register prefetch.
    const u32* yb = reinterpret_cast<const u32*>(g_y16) + (j0 >> 1) + cp;
    u32 yr[8];
    #pragma unroll
    for (int p = 0; p < 8; ++p) yr[p] = yb[(size_t)p * 512];

    // x stream: 4 half2 rows per d for this thread (one LDS.128).
    const uint2* xp = reinterpret_cast<const uint2*>(xs) + (rp4 >> 1);   // 8B units

    __half2 p0, p1, p2, p3;

    // 8-d body: consume yr[0..7], optionally refill for the next 8 d, advance pointers.
    #define QBODY(pf)                                                         \
    {                                                                         \
        _Pragma("unroll")                                                     \
        for (int q = 0; q < 8; ++q) {                                         \
            u32 ycur = yr[q];                                                 \
            if (pf) yr[q] = yb[(size_t)(q + 8) * 512];                        \
            __half2 y2 = *reinterpret_cast<__half2*>(&ycur);                  \
            uint4 xv = *reinterpret_cast<const uint4*>(xp + q * 4);           \
            __half2 x0 = *reinterpret_cast<__half2*>(&xv.x);                  \
            __half2 x1 = *reinterpret_cast<__half2*>(&xv.y);                  \
            __half2 x2 = *reinterpret_cast<__half2*>(&xv.z);                  \
            __half2 x3 = *reinterpret_cast<__half2*>(&xv.w);                  \
            p0 = __hadd2(p0, h2abs_alu(__hsub2(x0, y2)));                     \
            p1 = __hadd2(p1, h2abs_alu(__hsub2(x1, y2)));                     \
            p2 = __hadd2(p2, h2abs_alu(__hsub2(x2, y2)));                     \
            p3 = __hadd2(p3, h2abs_alu(__hsub2(x3, y2)));                     \
        }                                                                     \
        yb += 8 * 512;                                                        \
        xp += 32;                                                             \
    }

    #define UPCONV()                                                          \
    {                                                                         \
        float2 f0 = __half22float2(p0), f1 = __half22float2(p1);              \
        float2 f2 = __half22float2(p2), f3 = __half22float2(p3);              \
        facc[0].x += f0.x; facc[0].y += f0.y;                                 \
        facc[1].x += f1.x; facc[1].y += f1.y;                                 \
        facc[2].x += f2.x; facc[2].y += f2.y;                                 \
        facc[3].x += f3.x; facc[3].y += f3.y;                                 \
    }

    const __half2 hz = __float2half2_rn(0.f);
    // 15 full 16-d chunks with prefetch, then the final chunk (no prefetch on last body).
    for (int c = 0; c < 15; ++c) {
        p0 = hz; p1 = hz; p2 = hz; p3 = hz;
        QBODY(true);
        QBODY(true);
        UPCONV();
    }
    p0 = hz; p1 = hz; p2 = hz; p3 = hz;
    QBODY(true);
    QBODY(false);
    UPCONV();
    #undef QBODY
    #undef UPCONV

    // Epilogue: store s = -dist to gmem + smem transpose buffer.
    float sl[4], sh[4];
    #pragma unroll
    for (int r = 0; r < 4; ++r) { sl[r] = -facc[r].x; sh[r] = -facc[r].y; }

    const int ib = i0 + rp4;
    const int j = j0 + 2 * cp;
    #pragma unroll
    for (int r = 0; r < 4; ++r) {
        *reinterpret_cast<float2*>(g_S + (size_t)(ib + r) * Mm + j) = make_float2(sl[r], sh[r]);
        *reinterpret_cast<float2*>(&sbuf[rp4 + r][2 * cp]) = make_float2(sl[r], sh[r]);
    }
    __syncthreads();

    // Column partials over this block's 8 rows (thread per column).
    {
        const int c = t;                       // column j0+c
        float v0 = sbuf[0][c], v1 = sbuf[1][c], v2 = sbuf[2][c], v3 = sbuf[3][c];
        float v4 = sbuf[4][c], v5 = sbuf[5][c], v6 = sbuf[6][c], v7 = sbuf[7][c];
        float m = fmaxf(fmaxf(fmaxf(v0, v1), fmaxf(v2, v3)),
                        fmaxf(fmaxf(v4, v5), fmaxf(v6, v7)));
        float e = __expf(v0 - m) + __expf(v1 - m) + __expf(v2 - m) + __expf(v3 - m) +
                  __expf(v4 - m) + __expf(v5 - m) + __expf(v6 - m) + __expf(v7 - m);
        g_pm[(size_t)(j0 + c) * NGRP + rg] = m;
        g_ps[(size_t)(j0 + c) * NGRP + rg] = e;
    }

    // Row partials over this block's 128 cols (warp w handles rows 2w, 2w+1).
    #pragma unroll
    for (int rr = 2 * w; rr < 2 * w + 2; ++rr) {
        float a0 = sbuf[rr][lane],      a1 = sbuf[rr][lane + 32];
        float a2 = sbuf[rr][lane + 64], a3 = sbuf[rr][lane + 96];
        float lm = fmaxf(fmaxf(a0, a1), fmaxf(a2, a3));
        lm = warpMax(lm);
        float le = __expf(a0 - lm) + __expf(a1 - lm) + __expf(a2 - lm) + __expf(a3 - lm);
        le = warpSum(le);
        if (lane == 0) {
            g_rpm[(size_t)(i0 + rr) * 8 + ct] = lm;
            g_rps[(size_t)(i0 + rr) * 8 + ct] = le;
        }
    }
}

// ===================== K2: combine partials (cols: blocks 0..127; rows: 128..131) ========
__global__ __launch_bounds__(256) void k2_combine()
{
    const int bid = blockIdx.x;
    if (bid < 128) {
        // warp per column, 128 partials each
        const int w = threadIdx.x >> 5, lane = threadIdx.x & 31;
        const int j = bid * 8 + w;
        const float4 m4 = reinterpret_cast<const float4*>(g_pm + (size_t)j * NGRP)[lane];
        const float4 s4 = reinterpret_cast<const float4*>(g_ps + (size_t)j * NGRP)[lane];

        float m = fmaxf(fmaxf(m4.x, m4.y), fmaxf(m4.z, m4.w));
        m = warpMax(m);
        float s = s4.x * __expf(m4.x - m) + s4.y * __expf(m4.y - m) +
                  s4.z * __expf(m4.z - m) + s4.w * __expf(m4.w - m);
        s = warpSum(s);
        if (lane == 0) { g_cm[j] = m; g_cinv[j] = 1.0f / s; }
    } else {
        // thread per row, 8 partials each
        const int i = (bid - 128) * 256 + threadIdx.x;
        float4 ma = reinterpret_cast<const float4*>(g_rpm + (size_t)i * 8)[0];
        float4 mb = reinterpret_cast<const float4*>(g_rpm + (size_t)i * 8)[1];
        float4 sa = reinterpret_cast<const float4*>(g_rps + (size_t)i * 8)[0];
        float4 sb = reinterpret_cast<const float4*>(g_rps + (size_t)i * 8)[1];
        float m = fmaxf(fmaxf(fmaxf(ma.x, ma.y), fmaxf(ma.z, ma.w)),
                        fmaxf(fmaxf(mb.x, mb.y), fmaxf(mb.z, mb.w)));
        float s = sa.x * __expf(ma.x - m) + sa.y * __expf(ma.y - m) +
                  sa.z * __expf(ma.z - m) + sa.w * __expf(ma.w - m) +
                  sb.x * __expf(mb.x - m) + sb.y * __expf(mb.y - m) +
                  sb.z * __expf(mb.z - m) + sb.w * __expf(mb.w - m);
        g_rm[i] = m;
        g_rinv[i] = 1.0f / s;
    }
}

// ===================== K3: high-MLP elementwise + last-block combine =====================
// 256 blocks x 256 threads. Block b owns rows 4b..4b+3; warp-pair per row.
// Thread: row r = 4b + (t>>6), 4 float4s at float4-cols (t&63) + 64q — 12 loads in flight.
__global__ __launch_bounds__(256) void k3_final(float* __restrict__ out)
{
    __shared__ float shn[8], shd[8];
    __shared__ u32 sh_last;
    const int t = threadIdx.x;
    const int w = t >> 5, lane = t & 31;
    const int r = blockIdx.x * 4 + (t >> 6);
    const int c0 = t & 63;                     // base float4-column

    const float rm = g_rm[r];
    const float rinv = g_rinv[r];
    const float4* Srow = reinterpret_cast<const float4*>(g_S + (size_t)r * Mm);
    const float4* CM = reinterpret_cast<const float4*>(g_cm);
    const float4* CI = reinterpret_cast<const float4*>(g_cinv);

    // Issue all 12 independent loads first (MLP=12).
    float4 s4[4], cm4[4], ci4[4];
    #pragma unroll
    for (int q = 0; q < 4; ++q) s4[q] = Srow[c0 + 64 * q];
    #pragma unroll
    for (int q = 0; q < 4; ++q) cm4[q] = CM[c0 + 64 * q];
    #pragma unroll
    for (int q = 0; q < 4; ++q) ci4[q] = CI[c0 + 64 * q];

    float num = 0.f, den = 0.f;
    #pragma unroll
    for (int q = 0; q < 4; ++q) {
        {
            float a = __expf(s4[q].x - rm) * rinv, b = __expf(s4[q].x - cm4[q].x) * ci4[q].x;
            float u = a + b - a * b; num += u * s4[q].x; den += u;
        }
        {
            float a = __expf(s4[q].y - rm) * rinv, b = __expf(s4[q].y - cm4[q].y) * ci4[q].y;
            float u = a + b - a * b; num += u * s4[q].y; den += u;
        }
        {
            float a = __expf(s4[q].z - rm) * rinv, b = __expf(s4[q].z - cm4[q].z) * ci4[q].z;
            float u = a + b - a * b; num += u * s4[q].z; den += u;
        }
        {
            float a = __expf(s4[q].w - rm) * rinv, b = __expf(s4[q].w - cm4[q].w) * ci4[q].w;
            float u = a + b - a * b; num += u * s4[q].w; den += u;
        }
    }

    num = warpSum(num); den = warpSum(den);
    if (lane == 0) { shn[w] = num; shd[w] = den; }
    __syncthreads();
    if (w == 0) {
        float n = (lane < 8) ? shn[lane] : 0.f;
        float d = (lane < 8) ? shd[lane] : 0.f;
        n = warpSum(n); d = warpSum(d);
        if (lane == 0) { g_num[blockIdx.x] = n; g_den[blockIdx.x] = d; }
    }

    // ---- last-block deterministic combine ----
    __threadfence();
    __syncthreads();
    if (t == 0) sh_last = atomicAdd(&g_done, 1u);
    __syncthreads();
    if (sh_last != K3_BLOCKS - 1) return;

    __threadfence();   // acquire side: see all blocks' g_num/g_den
    float n2 = (t < K3_BLOCKS) ? g_num[t] : 0.f;
    float d2 = (t < K3_BLOCKS) ? g_den[t] : 0.f;
    n2 = warpSum(n2); d2 = warpSum(d2);
    if (lane == 0) { shn[w] = n2; shd[w] = d2; }
    __syncthreads();
    if (w == 0) {
        float n = (lane < 8) ? shn[lane] : 0.f;
        float d = (lane < 8) ? shd[lane] : 0.f;
        n = warpSum(n); d = warpSum(d);
        if (lane == 0) {
            out[0] = n / d;
            g_done = 0;          // self-reset for next graph replay
        }
    }
}

extern "C" void kernel_launch(void* const* d_in, const int* in_sizes, int n_in,
                              void* d_out, int out_size)
{
    const float* zx = (const float*)d_in[0];
    const float* zy = (const float*)d_in[1];
    float* out = (float*)d_out;

    k0_quant<<<(Dd * Mm) / 512, 512>>>(zy);
    k1_scores<<<(Nn / RG) * (Mm / CT), 128>>>(zx);
    k2_combine<<<132, 256>>>();
    k3_final<<<K3_BLOCKS, 256>>>(out);
}

// round 14
// speedup vs baseline: 1.2880x; 1.0504x over previous
#include <cuda_runtime.h>
#include <cuda_fp16.h>

#define Dd 256
#define Nn 1024
#define Mm 1024
#define RG 8                  // rows per K1 tile
#define CT 128                // cols per K1 tile
#define NGRP 128              // 8-row column-partial groups (1024/8)
#define K3_BLOCKS 256

typedef unsigned long long u64;
typedef unsigned int u32;

// Scratch (static __device__ — no runtime allocation)
__device__ __half g_y16[Dd * Mm];         // fp16 copy of z_y (512 KB)
__device__ float g_S[Nn * Mm];            // score matrix s = -L1dist (4 MB)
__device__ float g_pm[Mm * NGRP];         // col partial max, transposed [col][group]
__device__ float g_ps[Mm * NGRP];         // col partial expsum
__device__ float g_rpm[Nn * 8];           // row partial max [row][colgroup]
__device__ float g_rps[Nn * 8];           // row partial expsum
__device__ float g_cm[Mm], g_cinv[Mm];    // column max, 1/colsum
__device__ float g_rm[Nn], g_rinv[Nn];    // row max, 1/rowsum
__device__ float g_num[K3_BLOCKS], g_den[K3_BLOCKS];
__device__ u32 g_done = 0;                // k3 last-block counter (self-resetting)

__device__ __forceinline__ float warpMax(float v) {
    #pragma unroll
    for (int o = 16; o; o >>= 1) v = fmaxf(v, __shfl_xor_sync(0xffffffffu, v, o));
    return v;
}
__device__ __forceinline__ float warpSum(float v) {
    #pragma unroll
    for (int o = 16; o; o >>= 1) v += __shfl_xor_sync(0xffffffffu, v, o);
    return v;
}

// ===================== K0: quantize z_y to fp16 =====================
__global__ __launch_bounds__(512) void k0_quant(const float* __restrict__ zy)
{
    const int i = blockIdx.x * 512 + threadIdx.x;       // grid covers 256K elems
    g_y16[i] = __float2half(zy[i]);
}

// ===================== K1: max-trick fp16 scores + partials =====================
// s(i,j) = Sx_i + Sy_j - 2*Sum_d max(x,y).
// 1024 blocks (128 row-groups x 8 col-tiles), 128 threads.
// Thread t: col pair cp = t&63 (cols j0+2cp, j0+2cp+1), rows rp4..rp4+3.
// Mainloop per d: 4 HMNMX2 (alu) + 4 HADD2 (fma, M accum) + 1 HADD2 (Sy accum).
__global__ __launch_bounds__(128, 8) void k1_scores(
    const float* __restrict__ zx)
{
    __shared__ __align__(16) __half2 xs[Dd][RG];   // duplicated (x,x) fp16 pairs, 8KB
    __shared__ __align__(16) float sbuf[RG][CT];   // epilogue scratch, 4KB
    __shared__ float sxr[RG];                      // per-row x sums
    const int t = threadIdx.x;
    const int w = t >> 5, lane = t & 31;
    const int rg = blockIdx.x >> 3;
    const int ct = blockIdx.x & 7;
    const int i0 = rg * RG, j0 = ct * CT;

    for (int idx = t; idx < Dd * RG; idx += 128) {
        int d = idx >> 3, r = idx & 7;
        __half h = __float2half(zx[d * Nn + i0 + r]);
        xs[d][r] = __half2half2(h);
    }
    __syncthreads();

    // Sx per row from xs (fp32). Thread t: row t&7, 16-d chunk t>>3.
    {
        int r = t & 7, c = t >> 3;
        float s = 0.f;
        #pragma unroll
        for (int dd = 0; dd < 16; ++dd)
            s += __half2float(*reinterpret_cast<const __half*>(&xs[c * 16 + dd][r]));
        sbuf[r][c] = s;
    }
    __syncthreads();
    if (t < RG) {
        float s = 0.f;
        #pragma unroll
        for (int c = 0; c < 16; ++c) s += sbuf[t][c];
        sxr[t] = s;
    }
    __syncthreads();

    const int cp = t & 63;
    const int rp4 = (t >> 6) * 4;

    float2 facc[4];                                // M accumulators (2 cols x 4 rows)
    #pragma unroll
    for (int r = 0; r < 4; ++r) facc[r] = make_float2(0.f, 0.f);
    float2 fsy = make_float2(0.f, 0.f);            // Sy for this thread's 2 cols

    // y stream: half2 per lane per d; stride 512 half2 per d. Depth-8 register prefetch.
    const u32* yb = reinterpret_cast<const u32*>(g_y16) + (j0 >> 1) + cp;
    u32 yr[8];
    #pragma unroll
    for (int p = 0; p < 8; ++p) yr[p] = yb[(size_t)p * 512];

    // x stream: 4 half2 rows per d for this thread (one LDS.128).
    const uint2* xp = reinterpret_cast<const uint2*>(xs) + (rp4 >> 1);   // 8B units

    __half2 p0, p1, p2, p3, psy;

    // 8-d body: consume yr[0..7], optionally refill for the next 8 d, advance pointers.
    #define QBODY(pf)                                                         \
    {                                                                         \
        _Pragma("unroll")                                                     \
        for (int q = 0; q < 8; ++q) {                                         \
            u32 ycur = yr[q];                                                 \
            if (pf) yr[q] = yb[(size_t)(q + 8) * 512];                        \
            __half2 y2 = *reinterpret_cast<__half2*>(&ycur);                  \
            uint4 xv = *reinterpret_cast<const uint4*>(xp + q * 4);           \
            __half2 x0 = *reinterpret_cast<__half2*>(&xv.x);                  \
            __half2 x1 = *reinterpret_cast<__half2*>(&xv.y);                  \
            __half2 x2 = *reinterpret_cast<__half2*>(&xv.z);                  \
            __half2 x3 = *reinterpret_cast<__half2*>(&xv.w);                  \
            p0 = __hadd2(p0, __hmax2(x0, y2));                                \
            p1 = __hadd2(p1, __hmax2(x1, y2));                                \
            p2 = __hadd2(p2, __hmax2(x2, y2));                                \
            p3 = __hadd2(p3, __hmax2(x3, y2));                                \
            psy = __hadd2(psy, y2);                                           \
        }                                                                     \
        yb += 8 * 512;                                                        \
        xp += 32;                                                             \
    }

    #define UPCONV()                                                          \
    {                                                                         \
        float2 f0 = __half22float2(p0), f1 = __half22float2(p1);              \
        float2 f2 = __half22float2(p2), f3 = __half22float2(p3);              \
        float2 fy = __half22float2(psy);                                      \
        facc[0].x += f0.x; facc[0].y += f0.y;                                 \
        facc[1].x += f1.x; facc[1].y += f1.y;                                 \
        facc[2].x += f2.x; facc[2].y += f2.y;                                 \
        facc[3].x += f3.x; facc[3].y += f3.y;                                 \
        fsy.x += fy.x; fsy.y += fy.y;                                         \
    }

    const __half2 hz = __float2half2_rn(0.f);
    for (int c = 0; c < 15; ++c) {
        p0 = hz; p1 = hz; p2 = hz; p3 = hz; psy = hz;
        QBODY(true);
        QBODY(true);
        UPCONV();
    }
    p0 = hz; p1 = hz; p2 = hz; p3 = hz; psy = hz;
    QBODY(true);
    QBODY(false);
    UPCONV();
    #undef QBODY
    #undef UPCONV

    __syncthreads();   // sbuf about to be reused; xs reads done

    // Epilogue: s = Sx + Sy - 2M; store to gmem + smem transpose buffer.
    float sl[4], sh[4];
    #pragma unroll
    for (int r = 0; r < 4; ++r) {
        float sxv = sxr[rp4 + r];
        sl[r] = fmaf(-2.f, facc[r].x, sxv + fsy.x);
        sh[r] = fmaf(-2.f, facc[r].y, sxv + fsy.y);
    }

    const int ib = i0 + rp4;
    const int j = j0 + 2 * cp;
    #pragma unroll
    for (int r = 0; r < 4; ++r) {
        *reinterpret_cast<float2*>(g_S + (size_t)(ib + r) * Mm + j) = make_float2(sl[r], sh[r]);
        *reinterpret_cast<float2*>(&sbuf[rp4 + r][2 * cp]) = make_float2(sl[r], sh[r]);
    }
    __syncthreads();

    // Column partials over this block's 8 rows (thread per column).
    {
        const int c = t;                       // column j0+c
        float v0 = sbuf[0][c], v1 = sbuf[1][c], v2 = sbuf[2][c], v3 = sbuf[3][c];
        float v4 = sbuf[4][c], v5 = sbuf[5][c], v6 = sbuf[6][c], v7 = sbuf[7][c];
        float m = fmaxf(fmaxf(fmaxf(v0, v1), fmaxf(v2, v3)),
                        fmaxf(fmaxf(v4, v5), fmaxf(v6, v7)));
        float e = __expf(v0 - m) + __expf(v1 - m) + __expf(v2 - m) + __expf(v3 - m) +
                  __expf(v4 - m) + __expf(v5 - m) + __expf(v6 - m) + __expf(v7 - m);
        g_pm[(size_t)(j0 + c) * NGRP + rg] = m;
        g_ps[(size_t)(j0 + c) * NGRP + rg] = e;
    }

    // Row partials over this block's 128 cols (warp w handles rows 2w, 2w+1).
    #pragma unroll
    for (int rr = 2 * w; rr < 2 * w + 2; ++rr) {
        float a0 = sbuf[rr][lane],      a1 = sbuf[rr][lane + 32];
        float a2 = sbuf[rr][lane + 64], a3 = sbuf[rr][lane + 96];
        float lm = fmaxf(fmaxf(a0, a1), fmaxf(a2, a3));
        lm = warpMax(lm);
        float le = __expf(a0 - lm) + __expf(a1 - lm) + __expf(a2 - lm) + __expf(a3 - lm);
        le = warpSum(le);
        if (lane == 0) {
            g_rpm[(size_t)(i0 + rr) * 8 + ct] = lm;
            g_rps[(size_t)(i0 + rr) * 8 + ct] = le;
        }
    }
}

// ===================== K2: combine partials (cols: blocks 0..127; rows: 128..131) ========
__global__ __launch_bounds__(256) void k2_combine()
{
    const int bid = blockIdx.x;
    if (bid < 128) {
        const int w = threadIdx.x >> 5, lane = threadIdx.x & 31;
        const int j = bid * 8 + w;
        const float4 m4 = reinterpret_cast<const float4*>(g_pm + (size_t)j * NGRP)[lane];
        const float4 s4 = reinterpret_cast<const float4*>(g_ps + (size_t)j * NGRP)[lane];

        float m = fmaxf(fmaxf(m4.x, m4.y), fmaxf(m4.z, m4.w));
        m = warpMax(m);
        float s = s4.x * __expf(m4.x - m) + s4.y * __expf(m4.y - m) +
                  s4.z * __expf(m4.z - m) + s4.w * __expf(m4.w - m);
        s = warpSum(s);
        if (lane == 0) { g_cm[j] = m; g_cinv[j] = 1.0f / s; }
    } else {
        const int i = (bid - 128) * 256 + threadIdx.x;
        float4 ma = reinterpret_cast<const float4*>(g_rpm + (size_t)i * 8)[0];
        float4 mb = reinterpret_cast<const float4*>(g_rpm + (size_t)i * 8)[1];
        float4 sa = reinterpret_cast<const float4*>(g_rps + (size_t)i * 8)[0];
        float4 sb = reinterpret_cast<const float4*>(g_rps + (size_t)i * 8)[1];
        float m = fmaxf(fmaxf(fmaxf(ma.x, ma.y), fmaxf(ma.z, ma.w)),
                        fmaxf(fmaxf(mb.x, mb.y), fmaxf(mb.z, mb.w)));
        float s = sa.x * __expf(ma.x - m) + sa.y * __expf(ma.y - m) +
                  sa.z * __expf(ma.z - m) + sa.w * __expf(ma.w - m) +
                  sb.x * __expf(mb.x - m) + sb.y * __expf(mb.y - m) +
                  sb.z * __expf(mb.z - m) + sb.w * __expf(mb.w - m);
        g_rm[i] = m;
        g_rinv[i] = 1.0f / s;
    }
}

// ===================== K3: high-MLP elementwise + last-block combine =====================
// 256 blocks x 256 threads. Thread: row r = 4b + (t>>6), 4 float4s — 12 loads in flight.
__global__ __launch_bounds__(256) void k3_final(float* __restrict__ out)
{
    __shared__ float shn[8], shd[8];
    __shared__ u32 sh_last;
    const int t = threadIdx.x;
    const int w = t >> 5, lane = t & 31;
    const int r = blockIdx.x * 4 + (t >> 6);
    const int c0 = t & 63;                     // base float4-column

    const float rm = g_rm[r];
    const float rinv = g_rinv[r];
    const float4* Srow = reinterpret_cast<const float4*>(g_S + (size_t)r * Mm);
    const float4* CM = reinterpret_cast<const float4*>(g_cm);
    const float4* CI = reinterpret_cast<const float4*>(g_cinv);

    float4 s4[4], cm4[4], ci4[4];
    #pragma unroll
    for (int q = 0; q < 4; ++q) s4[q] = Srow[c0 + 64 * q];
    #pragma unroll
    for (int q = 0; q < 4; ++q) cm4[q] = CM[c0 + 64 * q];
    #pragma unroll
    for (int q = 0; q < 4; ++q) ci4[q] = CI[c0 + 64 * q];

    float num = 0.f, den = 0.f;
    #pragma unroll
    for (int q = 0; q < 4; ++q) {
        {
            float a = __expf(s4[q].x - rm) * rinv, b = __expf(s4[q].x - cm4[q].x) * ci4[q].x;
            float u = a + b - a * b; num += u * s4[q].x; den += u;
        }
        {
            float a = __expf(s4[q].y - rm) * rinv, b = __expf(s4[q].y - cm4[q].y) * ci4[q].y;
            float u = a + b - a * b; num += u * s4[q].y; den += u;
        }
        {
            float a = __expf(s4[q].z - rm) * rinv, b = __expf(s4[q].z - cm4[q].z) * ci4[q].z;
            float u = a + b - a * b; num += u * s4[q].z; den += u;
        }
        {
            float a = __expf(s4[q].w - rm) * rinv, b = __expf(s4[q].w - cm4[q].w) * ci4[q].w;
            float u = a + b - a * b; num += u * s4[q].w; den += u;
        }
    }

    num = warpSum(num); den = warpSum(den);
    if (lane == 0) { shn[w] = num; shd[w] = den; }
    __syncthreads();
    if (w == 0) {
        float n = (lane < 8) ? shn[lane] : 0.f;
        float d = (lane < 8) ? shd[lane] : 0.f;
        n = warpSum(n); d = warpSum(d);
        if (lane == 0) { g_num[blockIdx.x] = n; g_den[blockIdx.x] = d; }
    }

    // ---- last-block deterministic combine ----
    __threadfence();
    __syncthreads();
    if (t == 0) sh_last = atomicAdd(&g_done, 1u);
    __syncthreads();
    if (sh_last != K3_BLOCKS - 1) return;

    __threadfence();   // acquire side: see all blocks' g_num/g_den
    float n2 = (t < K3_BLOCKS) ? g_num[t] : 0.f;
    float d2 = (t < K3_BLOCKS) ? g_den[t] : 0.f;
    n2 = warpSum(n2); d2 = warpSum(d2);
    if (lane == 0) { shn[w] = n2; shd[w] = d2; }
    __syncthreads();
    if (w == 0) {
        float n = (lane < 8) ? shn[lane] : 0.f;
        float d = (lane < 8) ? shd[lane] : 0.f;
        n = warpSum(n); d = warpSum(d);
        if (lane == 0) {
            out[0] = n / d;
            g_done = 0;          // self-reset for next graph replay
        }
    }
}

extern "C" void kernel_launch(void* const* d_in, const int* in_sizes, int n_in,
                              void* d_out, int out_size)
{
    const float* zx = (const float*)d_in[0];
    const float* zy = (const float*)d_in[1];
    float* out = (float*)d_out;

    k0_quant<<<(Dd * Mm) / 512, 512>>>(zy);
    k1_scores<<<(Nn / RG) * (Mm / CT), 128>>>(zx);
    k2_combine<<<132, 256>>>();
    k3_final<<<K3_BLOCKS, 256>>>(out);
}